// round 17
// baseline (speedup 1.0000x reference)
#include <cuda_runtime.h>
#include <cuda_fp16.h>
#include <cstdint>

// ---------------------------------------------------------------------------
// B=32, N=1024 -> T=32768 tokens, d=256, C=1024
// o_cls (T x C) = l2norm(x) @ l2norm(e,0)
// o_seq (T x C) = l2norm(x) @ l2norm(w,0)
// new_db (d x C) = EMA codebook update
// TWO launches: fused(norm_x || build_bt+colsum) -> gemm(+finalize in shadow)
// Accumulators are SELF-CLEARING: device globals start zeroed (module load);
// the gemm finalize reads each g_num2 cell once and writes 0 back; the
// per-class scalars are cleared by the last of their 256 readers (ticket).
// Every call thus starts from a zeroed state with no prep kernel.
// GEMM: fp16 mma.sync, tile 128x128, 4 warps (warp tile 64x64), 128 thr/CTA,
// 2 CTAs/SM. Scatter: red.global.add.v4.f32 into [c][d] accumulator.
// ---------------------------------------------------------------------------

#define T_TOKENS 32768
#define DIM      256
#define NCLS     1024
#define ALPHA_F  0.9f
#define EPS_F    1.19e-07f

// GEMM tiling
#define BM 128
#define BN 128
#define BK 64                       // 64 fp16 = 128 bytes/row (SW128 atom)
#define STAGE  32768                // A 16KB + B 16KB
#define GEMM_SMEM (1024 + 3 * STAGE)   // ~97KB per CTA; x2 CTAs = 194KB/SM

// ---------------- device scratch (allocation-free, zero-init at load) ------
__device__ __align__(16) __half g_x16 [(size_t)T_TOKENS * DIM];   // normalized x, fp16
__device__ __align__(16) __half g_bt16[(size_t)2 * NCLS * DIM];   // [class][k]: rows 0..1023 = en, 1024..2047 = wn
__device__ __align__(16) float g_num2[NCLS * DIM];   // [c][d] scatter accumulator (self-clearing)
__device__ float g_cnt[NCLS];                        // self-clearing via ticket
__device__ float g_sumA[NCLS];
__device__ float g_sumNA[NCLS];
__device__ unsigned int g_tick[NCLS];                // reader ticket, returns to 0

// ---------------- PTX helpers (portable, sm_80+/sm_90+) --------------------
__device__ __forceinline__ uint32_t smem_u32(const void* p) {
    uint32_t a;
    asm("{ .reg .u64 t; cvta.to.shared.u64 t, %1; cvt.u32.u64 %0, t; }" : "=r"(a) : "l"(p));
    return a;
}
__device__ __forceinline__ void cpa16(uint32_t s, const void* g) {
    asm volatile("cp.async.cg.shared.global [%0], [%1], 16;" :: "r"(s), "l"(g));
}
#define CP_COMMIT() asm volatile("cp.async.commit_group;" ::: "memory")
#define CP_WAIT(n)  asm volatile("cp.async.wait_group %0;" :: "n"(n) : "memory")

#define LDSM_X4(r0, r1, r2, r3, addr) \
    asm volatile("ldmatrix.sync.aligned.m8n8.x4.shared.b16 {%0,%1,%2,%3}, [%4];" \
        : "=r"(r0), "=r"(r1), "=r"(r2), "=r"(r3) : "r"(addr))

#define MMA16816(d, a, b) \
    asm volatile("mma.sync.aligned.m16n8k16.row.col.f32.f16.f16.f32 " \
        "{%0,%1,%2,%3},{%4,%5,%6,%7},{%8,%9},{%0,%1,%2,%3};" \
        : "+f"((d)[0]), "+f"((d)[1]), "+f"((d)[2]), "+f"((d)[3]) \
        : "r"((a)[0]), "r"((a)[1]), "r"((a)[2]), "r"((a)[3]), \
          "r"((b)[0]), "r"((b)[1]))

// vectorized global reduction (PTX ISA 8.1, sm_90+): one op, 4 floats
__device__ __forceinline__ void redv4(float* p, float a, float b, float c, float d) {
    asm volatile("red.global.add.v4.f32 [%0], {%1, %2, %3, %4};"
        :: "l"(p), "f"(a), "f"(b), "f"(c), "f"(d) : "memory");
}

__device__ __forceinline__ uint32_t sw128(uint32_t bo) {
    return bo ^ ((bo >> 3) & 0x70);
}

// ---------------------------------------------------------------------------
// 1) fused: norm_x (blocks 0..4095) || build_bt with inline colsum (4096..4607)
// ---------------------------------------------------------------------------
__global__ void fused_norm_bt_kernel(const float* __restrict__ emb,
                                     const int*   __restrict__ labels,
                                     const float* __restrict__ anc,
                                     const float* __restrict__ w,
                                     const float* __restrict__ e)
{
    __shared__ float tile[32][33];
    __shared__ float ps[8][33];
    __shared__ float rs[32];

    if (blockIdx.x < 4096) {
        // ---------------- norm_x: 8 tokens per block -----------------------
        int gwarp = (blockIdx.x * blockDim.x + threadIdx.x) >> 5;
        int lane  = threadIdx.x & 31;

        const float* src = emb + (size_t)gwarp * DIM + lane * 8;
        float v[8];
        float4 v0 = *(const float4*)(src);
        float4 v1 = *(const float4*)(src + 4);
        v[0]=v0.x; v[1]=v0.y; v[2]=v0.z; v[3]=v0.w;
        v[4]=v1.x; v[5]=v1.y; v[6]=v1.z; v[7]=v1.w;

        float s = 0.f;
        #pragma unroll
        for (int j = 0; j < 8; j++) s += v[j] * v[j];
        #pragma unroll
        for (int o = 16; o > 0; o >>= 1) s += __shfl_xor_sync(0xFFFFFFFFu, s, o);
        float r = rsqrtf(fmaxf(s, 1e-12f));

        union { __half h[8]; float4 f; } H;
        #pragma unroll
        for (int j = 0; j < 8; j++) {
            v[j] *= r;
            H.h[j] = __float2half_rn(v[j]);
        }
        *(float4*)(g_x16 + (size_t)gwarp * DIM + lane * 8) = H.f;

        float a = anc[gwarp];
        int   c = labels[gwarp];
        if (a > 0.5f) {
            float* dst = g_num2 + (size_t)c * DIM + lane * 8;   // 32B-aligned
            redv4(dst,     v[0], v[1], v[2], v[3]);
            redv4(dst + 4, v[4], v[5], v[6], v[7]);
        }
        if (lane == 0) {
            atomicAdd(&g_cnt[c],   1.0f);
            atomicAdd(&g_sumA[c],  a);
            atomicAdd(&g_sumNA[c], 1.0f - a);
        }
    } else {
        // ------- build_bt: 512 blocks, colsum computed inline ---------------
        int cb = blockIdx.x - 4096;          // 0..511
        int bz = cb >> 8;                    // 0..1 (0=e, 1=w)
        int rr = cb & 255;
        int bx = rr & 31;                    // 0..31 c-tile
        int by = rr >> 5;                    // 0..7  d-tile

        const float* src = (bz == 0) ? e : w;
        const int c0 = bx * 32;
        const int d0 = by * 32;
        const int tx = threadIdx.x & 31;
        const int ty = threadIdx.x >> 5;

        // tile load (32x32 transpose staging)
        #pragma unroll
        for (int i = 0; i < 4; i++) {
            int dl = ty + i * 8;
            tile[dl][tx] = src[(size_t)(d0 + dl) * NCLS + c0 + tx];
        }
        // inline column sq-sums over all 256 dims (coalesced, L2-resident)
        float p = 0.0f;
        #pragma unroll 8
        for (int i = 0; i < 32; i++) {
            float v = src[(size_t)(ty + i * 8) * NCLS + c0 + tx];
            p += v * v;
        }
        ps[ty][tx] = p;
        __syncthreads();

        if (threadIdx.x < 32) {
            float s = 0.0f;
            #pragma unroll
            for (int k = 0; k < 8; k++) s += ps[k][threadIdx.x];
            rs[threadIdx.x] = rsqrtf(fmaxf(s, 1e-12f));
        }
        __syncthreads();

        #pragma unroll
        for (int i = 0; i < 4; i++) {
            int cl = ty + i * 8;
            float v = tile[tx][cl] * rs[cl];
            g_bt16[(size_t)(bz * NCLS + c0 + cl) * DIM + d0 + tx] = __float2half_rn(v);
        }
    }
}

// ---------------------------------------------------------------------------
// 2) fp16 HMMA GEMM (R12 config) + fused finalize (self-clearing) in the
//    prologue shadow.
// ---------------------------------------------------------------------------
__global__ __launch_bounds__(128, 2)
void gemm_hmma_kernel(float* __restrict__ o_cls, float* __restrict__ o_seq,
                      const float* __restrict__ w, const float* __restrict__ e,
                      float* __restrict__ db)
{
    extern __shared__ char dsm[];
    const int tid    = threadIdx.x;
    const int lane   = tid & 31;
    const int wid    = tid >> 5;    // 0..3
    const int warp_m = wid & 1;     // rows wm*64
    const int warp_n = wid >> 1;    // cols wn*64

    const int m0 = blockIdx.x * BM;
    const int n0 = blockIdx.y * BN;              // fused column space [0,2048)
    float* O = (n0 < NCLS) ? o_cls : o_seq;
    const int ncol0 = n0 & (NCLS - 1);

    uint32_t raw  = smem_u32(dsm);
    uint32_t dynu = (raw + 1023u) & ~1023u;

    // ---- per-thread ldmatrix base addresses (kk = 0), swizzled -------------
    // kk offset (kk*32, bits 5-6) applied by XOR: commutes with SW128 xor
    // because seg*16 (bit 4) and kk*32 (bits 5-6) are bit-disjoint.
    uint32_t a_base[4], b_base[4];
    {
        #pragma unroll
        for (int mf = 0; mf < 4; mf++) {
            int row = warp_m * 64 + mf * 16 + (lane & 15);
            a_base[mf] = sw128((uint32_t)(row * 128 + ((lane >> 4) * 16)));
        }
        int g = lane >> 3;
        #pragma unroll
        for (int bf = 0; bf < 4; bf++) {
            int row = warp_n * 64 + bf * 16 + (g >> 1) * 8 + (lane & 7);
            b_base[bf] = 16384u + sw128((uint32_t)(row * 128 + ((g & 1) * 16)));
        }
    }

    // ---- stage loader: chunk k0=c*64 -> stage (A @0, B @16384) -------------
    const int lr  = tid >> 3;       // 0..15
    const int lsg = tid & 7;        // 16B segment in row
    auto load_stage = [&](int chunk, int stage) {
        uint32_t sb = dynu + stage * STAGE;
        const int k0 = chunk * BK;
        #pragma unroll
        for (int i = 0; i < 8; i++) {
            int r = lr + i * 16;                 // 0..127
            uint32_t sw = sw128((uint32_t)(r * 128 + lsg * 16));
            cpa16(sb + sw,          g_x16  + (size_t)(m0 + r) * DIM + k0 + lsg * 8);
            cpa16(sb + 16384 + sw,  g_bt16 + (size_t)(n0 + r) * DIM + k0 + lsg * 8);
        }
        CP_COMMIT();
    };

    float acc[4][8][4] = {};   // [mfrag][nfrag][4] = 128 regs

    // ---- compute one 64-K chunk from a stage --------------------------------
    auto compute = [&](uint32_t sb) {
        #pragma unroll
        for (int kk = 0; kk < 4; kk++) {
            uint32_t koff = (uint32_t)(kk * 32);
            uint32_t a[4][4], b[8][2];
            #pragma unroll
            for (int mf = 0; mf < 4; mf++)
                LDSM_X4(a[mf][0], a[mf][1], a[mf][2], a[mf][3],
                        (sb + a_base[mf]) ^ koff);
            #pragma unroll
            for (int bf = 0; bf < 4; bf++) {
                uint32_t r0, r1, r2, r3;
                LDSM_X4(r0, r1, r2, r3, (sb + b_base[bf]) ^ koff);
                b[bf*2][0]   = r0; b[bf*2][1]   = r1;
                b[bf*2+1][0] = r2; b[bf*2+1][1] = r3;
            }
            #pragma unroll
            for (int mf = 0; mf < 4; mf++)
                #pragma unroll
                for (int nf = 0; nf < 8; nf++)
                    MMA16816(acc[mf][nf], a[mf], b[nf]);
        }
    };

    // ---- pipeline: 3 stages, 4 chunks ---------------------------------------
    load_stage(0, 0);        // g0
    load_stage(1, 1);        // g1
    load_stage(2, 2);        // g2

    // ---- fused finalize (self-clearing), hidden under cp.async --------------
    // fused_norm_bt completed before this kernel launched (stream order).
    // Each g_num2 cell has exactly one reader (bijective idx<->(c,d)): read
    // then clear. Per-class scalars have 256 readers: the last one (ticket)
    // clears them and resets the ticket, restoring the zeroed state for the
    // next call. Device globals start zeroed at module load.
    {
        int bid = blockIdx.y * gridDim.x + blockIdx.x;   // 0..4095
        int idx = bid * 64 + tid;                        // 64 per CTA
        if (tid < 64) {
            int c = idx & (NCLS - 1);
            int d = idx >> 10;
            float cnt = g_cnt[c];
            float sA  = g_sumA[c];
            float sNA = g_sumNA[c];
            float nm  = g_num2[c * DIM + d];
            g_num2[c * DIM + d] = 0.0f;                  // sole reader: safe clear

            float negAnc = (sA  > 0.5f) ? 1.0f : 0.0f;
            float posAnc = (sNA > 0.5f) ? 1.0f : 0.0f;
            float negCls = (cnt > 0.5f) ? 0.0f : 1.0f;
            float wv = w[idx];
            float ev = e[idx];
            float ema = 0.1f * (nm / (cnt + EPS_F));
            db[idx] = ALPHA_F * wv * negAnc + ema + wv * negCls + ev * posAnc;

            __threadfence();                             // order reads before ticket
            if (atomicAdd(&g_tick[c], 1u) == 255u) {     // last of 256 readers
                g_cnt[c]  = 0.0f;
                g_sumA[c] = 0.0f;
                g_sumNA[c] = 0.0f;
                __threadfence();
                g_tick[c] = 0u;                          // ticket back to 0
            }
        }
    }

    CP_WAIT(2); __syncthreads();       // g0 done
    compute(dynu);
    __syncthreads();                   // all warps done reading stage 0
    load_stage(3, 0);                  // g3

    CP_WAIT(2); __syncthreads();       // g1 done
    compute(dynu + STAGE);

    CP_WAIT(1); __syncthreads();       // g2 done
    compute(dynu + 2 * STAGE);

    CP_WAIT(0); __syncthreads();       // g3 done
    compute(dynu);

    // ---- epilogue: vectorized fp32 stores -----------------------------------
    #pragma unroll
    for (int mf = 0; mf < 4; mf++) {
        int row = m0 + warp_m * 64 + mf * 16 + (lane >> 2);
        #pragma unroll
        for (int nf = 0; nf < 8; nf++) {
            int col = ncol0 + warp_n * 64 + nf * 8 + 2 * (lane & 3);
            *(float2*)(O + (size_t)row * NCLS + col) =
                make_float2(acc[mf][nf][0], acc[mf][nf][1]);
            *(float2*)(O + (size_t)(row + 8) * NCLS + col) =
                make_float2(acc[mf][nf][2], acc[mf][nf][3]);
        }
    }
}

// ---------------------------------------------------------------------------
// launch: 2 kernels
// ---------------------------------------------------------------------------
extern "C" void kernel_launch(void* const* d_in, const int* in_sizes, int n_in,
                              void* d_out, int out_size)
{
    const float* emb = (const float*)d_in[0];
    const int*   obj = (const int*)  d_in[2];
    const float* anc = (const float*)d_in[3];
    const float* w   = (const float*)d_in[5];
    const float* e   = (const float*)d_in[6];

    float* out   = (float*)d_out;
    float* o_cls = out;
    float* o_seq = out + (size_t)T_TOKENS * NCLS;
    float* db    = out + (size_t)2 * T_TOKENS * NCLS;

    cudaFuncSetAttribute(gemm_hmma_kernel,
                         cudaFuncAttributeMaxDynamicSharedMemorySize, GEMM_SMEM);

    fused_norm_bt_kernel<<<4608, 256>>>(emb, obj, anc, w, e);

    dim3 grid(T_TOKENS / BM, 2 * NCLS / BN);     // (256, 16)
    gemm_hmma_kernel<<<grid, 128, GEMM_SMEM>>>(o_cls, o_seq, w, e, db);
}